// round 1
// baseline (speedup 1.0000x reference)
#include <cuda_runtime.h>
#include <math.h>

// Problem constants
#define NPOS   65536      // 8*8*32*32 positions
#define IDIM_  256
#define H_     8
#define DH_    64
#define HD_    512        // H*DH
#define ODIM_  256
#define TM     32         // positions per CTA
#define NT     256        // threads per CTA
#define QST    33         // padded stride for [512][33] column-major tiles
#define SCT    65         // padded stride for scores [32][65]
#define EPS_   1e-5f
#define SCALE_ 0.088388347648318447f   // 1/sqrt(128)

struct Smem {
    float Xs[TM][IDIM_];     // input tile, row-major        (32 KB)
    float qsT[HD_][QST];     // q / (later) v tile, c-major  (66 KB)
    float ksT[HD_][QST];     // k / (later) attn tile        (66 KB)
    float sc[TM][SCT];       // scores / probs [p][h*8+h']   (8.3 KB)
    float cds[TM][2];        // coords per position
};

// ---------------------------------------------------------------------------
// GEMM: dstT[c][p] = sum_k Xs[p][k] * W[k][c],  M=32, N=512, K=256.
// Thread (rg = tid>>5, cg = tid&31) computes rows rg*4..+3, cols cg*4+q+128*j2.
// W streamed from L2 with 1-iteration register prefetch.
// ---------------------------------------------------------------------------
__device__ __forceinline__ void gemm_proj(const float* __restrict__ W,
                                          const Smem& S, float (*dstT)[QST],
                                          int tid)
{
    const int rg = tid >> 5, cg = tid & 31;
    float acc[4][16];
#pragma unroll
    for (int r = 0; r < 4; r++)
#pragma unroll
        for (int c = 0; c < 16; c++) acc[r][c] = 0.f;

    const float* Wb = W + cg * 4;
    float4 wc[4];
    float  xc[4];
#pragma unroll
    for (int j2 = 0; j2 < 4; j2++)
        wc[j2] = *reinterpret_cast<const float4*>(Wb + 128 * j2);
#pragma unroll
    for (int rr = 0; rr < 4; rr++) xc[rr] = S.Xs[rg * 4 + rr][0];

#pragma unroll 2
    for (int k = 0; k < IDIM_; k++) {
        float4 wn[4];
        float  xn[4];
        const int kn = (k + 1 < IDIM_) ? (k + 1) : k;
#pragma unroll
        for (int j2 = 0; j2 < 4; j2++)
            wn[j2] = *reinterpret_cast<const float4*>(Wb + kn * HD_ + 128 * j2);
#pragma unroll
        for (int rr = 0; rr < 4; rr++) xn[rr] = S.Xs[rg * 4 + rr][kn];

#pragma unroll
        for (int rr = 0; rr < 4; rr++) {
            const float x = xc[rr];
#pragma unroll
            for (int j2 = 0; j2 < 4; j2++) {
                acc[rr][j2 * 4 + 0] += x * wc[j2].x;
                acc[rr][j2 * 4 + 1] += x * wc[j2].y;
                acc[rr][j2 * 4 + 2] += x * wc[j2].z;
                acc[rr][j2 * 4 + 3] += x * wc[j2].w;
            }
        }
#pragma unroll
        for (int j2 = 0; j2 < 4; j2++) wc[j2] = wn[j2];
#pragma unroll
        for (int rr = 0; rr < 4; rr++) xc[rr] = xn[rr];
    }

    // store column-major (4-way conflict on scalar STS, negligible volume)
#pragma unroll
    for (int rr = 0; rr < 4; rr++)
#pragma unroll
        for (int j2 = 0; j2 < 4; j2++)
#pragma unroll
            for (int q = 0; q < 4; q++)
                dstT[cg * 4 + q + 128 * j2][rg * 4 + rr] = acc[rr][j2 * 4 + q];
}

// ---------------------------------------------------------------------------
// Per-(position p, head h): bias add + LayerNorm(64) + coordinate rotation.
// Reads/writes column h*64..h*64+63 of T at lane p (conflict-free: lanes = p).
// ---------------------------------------------------------------------------
__device__ __forceinline__ void ln_rotate(float (*T)[QST],
                                          const float* __restrict__ bias,
                                          const float* __restrict__ g,
                                          const float* __restrict__ b,
                                          float coord, int p, int h)
{
    float v[DH_];
    float mu = 0.f;
#pragma unroll
    for (int j = 0; j < DH_; j++) {
        v[j] = T[h * DH_ + j][p] + bias[j];
        mu += v[j];
    }
    mu *= (1.f / DH_);
    float var = 0.f;
#pragma unroll
    for (int j = 0; j < DH_; j++) {
        const float d = v[j] - mu;
        var += d * d;
    }
    const float rs = rsqrtf(var * (1.f / DH_) + EPS_);
#pragma unroll
    for (int j = 0; j < DH_; j++) v[j] = (v[j] - mu) * rs * g[j] + b[j];

#pragma unroll
    for (int j = 0; j < DH_ / 2; j++) {
        float s, c;
        sincosf(coord * (float)j, &s, &c);
        const float f  = v[j];
        const float gg = v[j + DH_ / 2];
        T[h * DH_ + j][p]            = c + (c * f - s * gg);
        T[h * DH_ + DH_ / 2 + j][p]  = s + (s * f + c * gg);
    }
}

// ---------------------------------------------------------------------------
// Fused kernel: projections + LN + rotation + 8x8 attention + output GEMM
// ---------------------------------------------------------------------------
__global__ void __launch_bounds__(NT, 1)
semattn_fused_kernel(const float* __restrict__ nodal,
                     const float* __restrict__ coords,
                     const float* __restrict__ WQ,
                     const float* __restrict__ WK,
                     const float* __restrict__ WV,
                     const float* __restrict__ biasQ,
                     const float* __restrict__ biasK,
                     const float* __restrict__ lnQg,
                     const float* __restrict__ lnQb,
                     const float* __restrict__ lnKg,
                     const float* __restrict__ lnKb,
                     const float* __restrict__ Wout,
                     const float* __restrict__ bout,
                     float* __restrict__ out)
{
    extern __shared__ float smem_f[];
    Smem& S = *reinterpret_cast<Smem*>(smem_f);
    const int  tid  = threadIdx.x;
    const long pos0 = (long)blockIdx.x * TM;

    // ---- load X tile, coords; zero scores ----
    {
        const float4* xin = reinterpret_cast<const float4*>(nodal + pos0 * IDIM_);
        float4* xs = reinterpret_cast<float4*>(&S.Xs[0][0]);
#pragma unroll
        for (int i = 0; i < (TM * IDIM_ / 4) / NT; i++)
            xs[tid + i * NT] = xin[tid + i * NT];
        if (tid < TM * 2)
            (&S.cds[0][0])[tid] = coords[pos0 * 2 + tid];
        for (int i = tid; i < TM * SCT; i += NT)
            (&S.sc[0][0])[i] = 0.f;
    }
    __syncthreads();

    const int h = tid >> 5;   // head (warp id)
    const int p = tid & 31;   // position within tile (lane)
    const int rg = tid >> 5, cg = tid & 31;

    // ================= Phase A: Q/K projections, LN+rotate, scores ==========
#pragma unroll
    for (int n = 0; n < 2; n++) {
        gemm_proj(WQ + n * IDIM_ * HD_, S, S.qsT, tid);
        gemm_proj(WK + n * IDIM_ * HD_, S, S.ksT, tid);
        __syncthreads();
        {
            const float cd = S.cds[p][n];
            ln_rotate(S.qsT, biasQ + (n * H_ + h) * DH_, lnQg + n * DH_,
                      lnQb + n * DH_, cd, p, h);
            ln_rotate(S.ksT, biasK + (n * H_ + h) * DH_, lnKg + n * DH_,
                      lnKb + n * DH_, cd, p, h);
        }
        __syncthreads();
        {   // scores[p][h][h'] += q_n[p,h,:] . k_n[p,h',:]
            float qreg[DH_];
#pragma unroll
            for (int j = 0; j < DH_; j++) qreg[j] = S.qsT[h * DH_ + j][p];
#pragma unroll
            for (int h2 = 0; h2 < H_; h2++) {
                float a = 0.f;
#pragma unroll
                for (int j = 0; j < DH_; j++)
                    a += qreg[j] * S.ksT[h2 * DH_ + j][p];
                S.sc[p][h * H_ + h2] += a;
            }
        }
        __syncthreads();
    }

    // ================= softmax over h' (one row per thread) =================
    {
        float r[H_];
        float mx = -1e30f;
#pragma unroll
        for (int j = 0; j < H_; j++) {
            r[j] = S.sc[p][h * H_ + j] * SCALE_;
            mx = fmaxf(mx, r[j]);
        }
        float sum = 0.f;
#pragma unroll
        for (int j = 0; j < H_; j++) {
            r[j] = expf(r[j] - mx);
            sum += r[j];
        }
        const float inv = 1.f / sum;
#pragma unroll
        for (int j = 0; j < H_; j++) S.sc[p][h * H_ + j] = r[j] * inv;
    }
    __syncthreads();

    // ================= Phase B: V projection, attn mix, output GEMM =========
    float oacc[4][8];
#pragma unroll
    for (int rr = 0; rr < 4; rr++)
#pragma unroll
        for (int c = 0; c < 8; c++) oacc[rr][c] = 0.f;

#pragma unroll
    for (int n = 0; n < 2; n++) {
        gemm_proj(WV + n * IDIM_ * HD_, S, S.qsT, tid);   // vsT in qsT
        __syncthreads();
        {   // attnT[h*64+j][p] = sum_h' P[p][h][h'] * v[p][h'][j]
            float pr[H_];
#pragma unroll
            for (int h2 = 0; h2 < H_; h2++) pr[h2] = S.sc[p][h * H_ + h2];
#pragma unroll
            for (int j = 0; j < DH_; j++) {
                float a = 0.f;
#pragma unroll
                for (int h2 = 0; h2 < H_; h2++)
                    a += pr[h2] * S.qsT[h2 * DH_ + j][p];
                S.ksT[h * DH_ + j][p] = a;                // attnT in ksT
            }
        }
        __syncthreads();
        {   // out[p][:] += attn_n[p][:] @ Wout[rows for this n]
            const float* Wb = Wout + cg * 4;
            int r0 = n * DH_;                             // row for k=0
            float4 w0 = *reinterpret_cast<const float4*>(Wb + r0 * ODIM_);
            float4 w1 = *reinterpret_cast<const float4*>(Wb + r0 * ODIM_ + 128);
            float  ac[4];
#pragma unroll
            for (int rr = 0; rr < 4; rr++) ac[rr] = S.ksT[0][rg * 4 + rr];

#pragma unroll 2
            for (int k = 0; k < HD_; k++) {
                float4 w0n, w1n;
                float  an[4];
                const int kn = (k + 1 < HD_) ? (k + 1) : k;
                const int rn = ((kn >> 6) << 7) + n * DH_ + (kn & 63);
                w0n = *reinterpret_cast<const float4*>(Wb + rn * ODIM_);
                w1n = *reinterpret_cast<const float4*>(Wb + rn * ODIM_ + 128);
#pragma unroll
                for (int rr = 0; rr < 4; rr++) an[rr] = S.ksT[kn][rg * 4 + rr];

#pragma unroll
                for (int rr = 0; rr < 4; rr++) {
                    const float a = ac[rr];
                    oacc[rr][0] += a * w0.x; oacc[rr][1] += a * w0.y;
                    oacc[rr][2] += a * w0.z; oacc[rr][3] += a * w0.w;
                    oacc[rr][4] += a * w1.x; oacc[rr][5] += a * w1.y;
                    oacc[rr][6] += a * w1.z; oacc[rr][7] += a * w1.w;
                }
                w0 = w0n; w1 = w1n;
#pragma unroll
                for (int rr = 0; rr < 4; rr++) ac[rr] = an[rr];
            }
        }
        __syncthreads();
    }

    // ================= epilogue: + bout, coalesced float4 store =============
#pragma unroll
    for (int rr = 0; rr < 4; rr++) {
        const long row = pos0 + rg * 4 + rr;
#pragma unroll
        for (int j2 = 0; j2 < 2; j2++) {
            const int c0 = cg * 4 + 128 * j2;
            float4 o;
            o.x = oacc[rr][j2 * 4 + 0] + bout[c0 + 0];
            o.y = oacc[rr][j2 * 4 + 1] + bout[c0 + 1];
            o.z = oacc[rr][j2 * 4 + 2] + bout[c0 + 2];
            o.w = oacc[rr][j2 * 4 + 3] + bout[c0 + 3];
            *reinterpret_cast<float4*>(out + row * ODIM_ + c0) = o;
        }
    }
}

// ---------------------------------------------------------------------------
extern "C" void kernel_launch(void* const* d_in, const int* in_sizes, int n_in,
                              void* d_out, int out_size)
{
    const float* nodal  = (const float*)d_in[0];
    const float* coords = (const float*)d_in[1];
    const float* WQ     = (const float*)d_in[2];
    const float* WK     = (const float*)d_in[3];
    const float* WV     = (const float*)d_in[4];
    const float* biasQ  = (const float*)d_in[5];
    const float* biasK  = (const float*)d_in[6];
    const float* lnQg   = (const float*)d_in[7];
    const float* lnQb   = (const float*)d_in[8];
    const float* lnKg   = (const float*)d_in[9];
    const float* lnKb   = (const float*)d_in[10];
    const float* Wout   = (const float*)d_in[11];
    const float* bout   = (const float*)d_in[12];
    float* out = (float*)d_out;

    const int smem_bytes = (int)sizeof(Smem);
    cudaFuncSetAttribute(semattn_fused_kernel,
                         cudaFuncAttributeMaxDynamicSharedMemorySize, smem_bytes);

    semattn_fused_kernel<<<NPOS / TM, NT, smem_bytes>>>(
        nodal, coords, WQ, WK, WV, biasQ, biasK,
        lnQg, lnQb, lnKg, lnKb, Wout, bout, out);
}